// round 16
// baseline (speedup 1.0000x reference)
#include <cuda_runtime.h>
#include <math.h>

// ---------------- constants ----------------
#define NN 500
#define NQ 125               // NN/4
#define PXd 1e-6
#define WLd 5.32e-7
#define FLd 0.1
#define FWHCd 1.5e-4
#define TWO_PI 6.283185307179586476925286766559
#define R_ 15
#define PSFW 31              // 2R+1
#define BB 8
#define NE 64
#define OUTW 198
#define TOT_OUT (BB*OUTW*OUTW)

// ---------------- device scratch (no runtime allocation allowed) ----------------
__device__ float2 d_fq[4*NN*NQ];     // field split by col parity mod 4 [p][500x125]
__device__ float2 d_F125[NQ*NQ];     // 125-pt DFT matrix (symmetric)
__device__ float  d_q[NN*NN];        // gamma/WL
__device__ float2 d_tq[4*NQ*NN];     // tmp split by row parity mod 4 [p][125x500]
__device__ float2 d_Ef[NN*NN];
__device__ float2 d_part[16*NN*NQ];  // split partials (8 used at ksplit=2)
__device__ float2 d_W1[PSFW*NN];     // (1/N) e^{+2pi i u*(235+y)/N}
__device__ float2 d_T[NE*PSFW*NN];   // stage-A output
__device__ float2 d_Ep[2*NE*PSFW*32];// stage-B v-split partials
__device__ float  d_psf[NE*PSFW*PSFW];
__device__ float  d_psfsum[NE];
__device__ float  d_canvas[BB*200*200];
__device__ float2 d_tw[NN];          // e^{-2pi i m / 500}
__device__ double d_w2d[NN];         // (WL * fftfreq)^2, double

__device__ __forceinline__ void cmac(float2& a, float2 x, float2 y) {
    a.x += x.x*y.x - x.y*y.y;
    a.y += x.x*y.y + x.y*y.x;
}
__device__ __forceinline__ float2 cmul(float2 x, float2 y) {
    return make_float2(x.x*y.x - x.y*y.y, x.x*y.y + x.y*y.x);
}

// ---------------- prep 0: twiddle table + freq^2 table (500 DP sincos/divs total) ----------------
__global__ void prep0() {
    int m = blockIdx.x * blockDim.x + threadIdx.x;
    if (m >= NN) return;
    double ang = -TWO_PI * (double)m / (double)NN;
    double s, c;
    sincos(ang, &s, &c);
    d_tw[m] = make_float2((float)c, (float)s);
    double f = (double)((m < NN/2) ? m : m - NN) / ((double)NN * PXd);
    double w = WLd * f;
    d_w2d[m] = w * w;
}

// ---------------- prep 1: field (split cols mod 4) + q (table-driven, no DP divs) ----------------
__global__ void prep1(const float* __restrict__ phase_mask) {
    int j = blockIdx.x * blockDim.x + threadIdx.x;
    int i = blockIdx.y;
    if (j >= NN) return;
    int idx = i*NN + j;

    float xi = (float)((i - NN/2) * PXd);
    float xj = (float)((j - NN/2) * PXd);
    float r2 = xi*xi + xj*xj;
    float inc = expf(-r2 * (float)(1.0/(2.0*FWHCd*FWHCd)));
    float c1 = (float)(3.141592653589793/(WLd*FLd)) * r2;   // small arg, no fmod
    float b1s, b1c;
    __sincosf(c1, &b1s, &b1c);
    b1s = -b1s;                                // exp(-i c1)

    float p = phase_mask[idx];
    float ps, pc;
    __sincosf(p, &ps, &pc);
    float2 f;
    f.x = inc * (pc*b1c - ps*b1s);
    f.y = inc * (pc*b1s + ps*b1c);
    d_fq[(j & 3)*(NN*NQ) + i*NQ + (j >> 2)] = f;

    // gamma arg: 2 cheap DP adds from table, then f32 sqrt
    float arg = (float)(1.0 - d_w2d[i] - d_w2d[j]);
    float gf = (arg > 0.f) ? sqrtf(arg) : 0.f;
    d_q[idx] = gf * (float)(1.0/WLd);
}

// ---------------- prep 2: W1, F125, zero canvas ----------------
__global__ void prep2() {
    int tid = blockIdx.x * blockDim.x + threadIdx.x;
    if (tid < PSFW*NN) {
        int y = tid / NN, u = tid % NN;
        int m = (u * (235 + y)) % NN;
        float2 t = d_tw[m];
        d_W1[tid] = make_float2(t.x * (1.0f/NN), -t.y * (1.0f/NN));
    }
    if (tid < NQ*NQ) {
        int a = tid / NQ, b = tid % NQ;
        d_F125[tid] = d_tw[(4*a*b) % NN];    // e^{-2pi i a b / 125}
    }
    if (tid < BB*200*200) d_canvas[tid] = 0.0f;
}

// ---------------- generic complex GEMM body, 64x64 tile, 4x4/thread ----------------
#define KT 16
__device__ __forceinline__ void cgemm_body(const float2* __restrict__ A, int lda,
                                           const float2* __restrict__ B, int ldb,
                                           float2* __restrict__ P,
                                           int M, int N, int kbeg, int kend) {
    __shared__ float2 As[2][KT][66];
    __shared__ float2 Bs[2][KT][66];
    int tid = threadIdx.x;
    int tx = tid & 15, ty = tid >> 4;
    int i0 = blockIdx.y * 64, j0 = blockIdx.x * 64;
    const float2 zero = make_float2(0.f, 0.f);
    float2 acc[4][4] = {};

    auto load_tile = [&](int k0, int b) {
        #pragma unroll
        for (int l = tid; l < 64*KT; l += 256) {       // A: coalesced over k
            int kk = l & 15, ii = l >> 4;
            int i = i0 + ii, k = k0 + kk;
            As[b][kk][ii] = (i < M && k < kend) ? A[i*lda + k] : zero;
        }
        #pragma unroll
        for (int l = tid; l < 64*KT; l += 256) {       // B: coalesced over j
            int jj = l & 63, kk = l >> 6;
            int j = j0 + jj, k = k0 + kk;
            Bs[b][kk][jj] = (j < N && k < kend) ? B[k*ldb + j] : zero;
        }
    };

    int nkt = (kend - kbeg + KT - 1) / KT;
    load_tile(kbeg, 0);
    __syncthreads();

    for (int t = 0; t < nkt; t++) {
        int cb = t & 1;
        if (t + 1 < nkt) load_tile(kbeg + (t + 1)*KT, cb ^ 1);
        #pragma unroll
        for (int kk = 0; kk < KT; kk++) {
            float4 a01 = *(const float4*)&As[cb][kk][4*ty];
            float4 a23 = *(const float4*)&As[cb][kk][4*ty + 2];
            float4 b01 = *(const float4*)&Bs[cb][kk][4*tx];
            float4 b23 = *(const float4*)&Bs[cb][kk][4*tx + 2];
            float2 a[4] = {{a01.x,a01.y},{a01.z,a01.w},{a23.x,a23.y},{a23.z,a23.w}};
            float2 b[4] = {{b01.x,b01.y},{b01.z,b01.w},{b23.x,b23.y},{b23.z,b23.w}};
            #pragma unroll
            for (int r = 0; r < 4; r++)
                #pragma unroll
                for (int c = 0; c < 4; c++)
                    cmac(acc[r][c], a[r], b[c]);
        }
        __syncthreads();
    }

    #pragma unroll
    for (int r = 0; r < 4; r++) {
        int i = i0 + 4*ty + r;
        if (i >= M) continue;
        #pragma unroll
        for (int c = 0; c < 4; c++) {
            int j = j0 + 4*tx + c;
            if (j < N) P[i*N + j] = acc[r][c];
        }
    }
}

// stage 1 gemms: S_p = field_p(500x125) @ F125(125x125), split-K x2 (chunks of 63)
// slice z = p*2+ks
__global__ void __launch_bounds__(256, 2) gemmS1() {
    int p = blockIdx.z >> 1, ks = blockIdx.z & 1;
    int kbeg = ks * 63, kend = min(kbeg + 63, NQ);
    cgemm_body(d_fq + p*(NN*NQ), NQ, d_F125, NQ,
               d_part + blockIdx.z * (NN*NQ), NN, NQ, kbeg, kend);
}

// combine 1: tmp[i,k] = sum_p tw[(k*p)%500] * S_p[i, k%125]; write split by i mod 4
__global__ void combine1() {
    int idx = blockIdx.x * blockDim.x + threadIdx.x;
    if (idx >= NN*NN) return;
    int i = idx / NN, k = idx % NN;
    int a = k % NQ;
    int base = i*NQ + a;
    float2 S[4];
    #pragma unroll
    for (int p = 0; p < 4; p++) {
        float2 s0 = d_part[(p*2+0)*(NN*NQ) + base];
        float2 s1 = d_part[(p*2+1)*(NN*NQ) + base];
        S[p] = make_float2(s0.x+s1.x, s0.y+s1.y);
    }
    float2 acc = S[0];
    float2 c1 = cmul(d_tw[k % NN], S[1]);
    float2 c2 = cmul(d_tw[(2*k) % NN], S[2]);
    float2 c3 = cmul(d_tw[(3*k) % NN], S[3]);
    acc.x += c1.x + c2.x + c3.x;
    acc.y += c1.y + c2.y + c3.y;
    d_tq[(i & 3)*(NQ*NN) + (i >> 2)*NN + k] = acc;
}

// stage 2 gemms: U_p = F125(125x125) @ tmp_p(125x500), split-K x2
__global__ void __launch_bounds__(256, 2) gemmS2() {
    int p = blockIdx.z >> 1, ks = blockIdx.z & 1;
    int kbeg = ks * 63, kend = min(kbeg + 63, NQ);
    cgemm_body(d_F125, NQ, d_tq + p*(NQ*NN), NN,
               d_part + blockIdx.z * (NQ*NN), NQ, NN, kbeg, kend);
}

// combine 2: Ef[a,b] = sum_p tw[(a*p)%500] * U_p[a%125, b]
__global__ void combine2() {
    int idx = blockIdx.x * blockDim.x + threadIdx.x;
    if (idx >= NN*NN) return;
    int a = idx / NN, b = idx % NN;
    int base = (a % NQ)*NN + b;
    float2 U[4];
    #pragma unroll
    for (int p = 0; p < 4; p++) {
        float2 s0 = d_part[(p*2+0)*(NQ*NN) + base];
        float2 s1 = d_part[(p*2+1)*(NQ*NN) + base];
        U[p] = make_float2(s0.x+s1.x, s0.y+s1.y);
    }
    float2 acc = U[0];
    float2 c1 = cmul(d_tw[a % NN], U[1]);
    float2 c2 = cmul(d_tw[(2*a) % NN], U[2]);
    float2 c3 = cmul(d_tw[(3*a) % NN], U[3]);
    acc.x += c1.x + c2.x + c3.x;
    acc.y += c1.y + c2.y + c3.y;
    d_Ef[idx] = acc;
}

// ---------------- stage A (radix-4 pruned inverse DFT over u) ----------------
// T[z][y][v] = sum_{u<125} C_{c(y)}[u,v] * W1[y,u],  c(y) = (235+y) mod 4
#define UT2 12
#define VT2 64
#define CSZ (UT2*VT2)        // per-class chunk: 768 float2
#define WSZ (UT2*32)         // w pack: [du][ty][s], 384 float2
#define NCH ((NQ + UT2 - 1) / UT2)   // 11 chunks

__global__ void __launch_bounds__(256) stageA(const float* __restrict__ zs) {
    int zi = blockIdx.y;
    int v0 = blockIdx.x * VT2;
    int tid = threadIdx.x;
    int tx = tid & 31;                 // v pair -> v0+2tx, +1
    int ty = tid >> 5;                 // 0..7 ; ys = ty+8s, all same class
    float z = zs[zi];

    __shared__ float2 C_sh[4*CSZ];     // [4][UT2][VT2]
    __shared__ float2 w_sh[WSZ];       // [UT2][8][4]

    float2 acc[4][2] = {};             // [s][vp]
    int cls = (3 + ty) & 3;

    for (int t = 0; t < NCH; t++) {
        if (t) __syncthreads();
        int u0 = t * UT2;
        // ---- fill w pack ----
        for (int l = tid; l < WSZ; l += 256) {
            int du = l >> 5, r = l & 31;
            int tty = r >> 2, s = r & 3;
            int y = tty + 8*s;
            float2 w = make_float2(0.f, 0.f);
            if (y < PSFW && u0 + du < NQ) w = d_W1[y*NN + u0 + du];
            w_sh[l] = w;
        }
        // ---- fill C classes (modulate + 2-level butterfly) ----
        for (int l = tid; l < UT2*VT2; l += 256) {
            int du = l >> 6, lv = l & 63;
            int vv = v0 + lv;
            int ua = u0 + du;
            float2 g[4];
            if (vv < NN && ua < NQ) {
                #pragma unroll
                for (int k = 0; k < 4; k++) {
                    int idx = (ua + 125*k)*NN + vv;
                    float2 ef = d_Ef[idx];
                    float r = d_q[idx] * z;
                    r = r - rintf(r);
                    float s, c;
                    __sincosf(6.2831853071795864f * r, &s, &c);
                    g[k] = make_float2(ef.x*c - ef.y*s, ef.x*s + ef.y*c);
                }
            } else {
                g[0] = g[1] = g[2] = g[3] = make_float2(0.f, 0.f);
            }
            float2 A0 = make_float2(g[0].x + g[2].x, g[0].y + g[2].y);
            float2 A1 = make_float2(g[1].x + g[3].x, g[1].y + g[3].y);
            float2 B0 = make_float2(g[0].x - g[2].x, g[0].y - g[2].y);
            float2 B1 = make_float2(g[1].x - g[3].x, g[1].y - g[3].y);
            int off = du*VT2 + lv;
            C_sh[0*CSZ + off] = make_float2(A0.x + A1.x, A0.y + A1.y);
            C_sh[1*CSZ + off] = make_float2(B0.x - B1.y, B0.y + B1.x);  // B0 + i*B1
            C_sh[2*CSZ + off] = make_float2(A0.x - A1.x, A0.y - A1.y);
            C_sh[3*CSZ + off] = make_float2(B0.x + B1.y, B0.y - B1.x);  // B0 - i*B1
        }
        __syncthreads();
        // ---- accumulate ----
        const float2* Cc = C_sh + cls*CSZ;
        #pragma unroll
        for (int du = 0; du < UT2; du++) {
            float4 cv = *(const float4*)&Cc[du*VT2 + 2*tx];
            float2 c0 = make_float2(cv.x, cv.y), c1 = make_float2(cv.z, cv.w);
            const float2* wp = &w_sh[du*32 + ty*4];
            float4 wA = *(const float4*)(wp);
            float4 wB = *(const float4*)(wp + 2);
            float2 w0 = make_float2(wA.x, wA.y), w1 = make_float2(wA.z, wA.w);
            float2 w2 = make_float2(wB.x, wB.y), w3 = make_float2(wB.z, wB.w);
            cmac(acc[0][0], w0, c0); cmac(acc[0][1], w0, c1);
            cmac(acc[1][0], w1, c0); cmac(acc[1][1], w1, c1);
            cmac(acc[2][0], w2, c0); cmac(acc[2][1], w2, c1);
            cmac(acc[3][0], w3, c0); cmac(acc[3][1], w3, c1);
        }
    }
    #pragma unroll
    for (int s = 0; s < 4; s++) {
        int y = ty + 8*s;
        if (y >= PSFW) continue;
        #pragma unroll
        for (int vp = 0; vp < 2; vp++) {
            int v = v0 + 2*tx + vp;
            if (v < NN) d_T[(zi*PSFW + y)*NN + v] = acc[s][vp];
        }
    }
}

// ---------------- stage B1: E-partials over v halves (grid (2, NE)) ----------------
__global__ void stageB1() {
    int vs = blockIdx.x;                       // 0,1: v in [vs*250, vs*250+250)
    int zi = blockIdx.y;
    int tx = threadIdx.x;                      // 0..31 (x)
    int ty = threadIdx.y;                      // 0..7  (y stride 8)
    int tid = ty*32 + tx;
    int vbeg = vs * 250, vend = vbeg + 250;

    __shared__ float2 T_sh[PSFW*64];
    __shared__ float2 W_sh[64*32];             // [vl][x]
    float2 acc[4] = {};

    for (int v0 = vbeg; v0 < vend; v0 += 64) {
        for (int l = tid; l < PSFW*64; l += 256) {
            int y = l / 64, vl = l % 64;
            int v = v0 + vl;
            T_sh[l] = (v < vend) ? d_T[(zi*PSFW + y)*NN + v] : make_float2(0.f, 0.f);
        }
        for (int l = tid; l < 64*32; l += 256) {
            int vl = l / 32, x = l % 32;
            int v = v0 + vl;
            W_sh[l] = (v < vend && x < PSFW) ? d_W1[x*NN + v] : make_float2(0.f, 0.f);
        }
        __syncthreads();
        #pragma unroll 8
        for (int vl = 0; vl < 64; vl++) {
            float2 w = W_sh[vl*32 + tx];
            #pragma unroll
            for (int k = 0; k < 4; k++) {
                int y = ty + 8*k;
                float2 t = T_sh[(y < PSFW ? y : PSFW-1)*64 + vl];
                acc[k].x += t.x*w.x - t.y*w.y;
                acc[k].y += t.x*w.y + t.y*w.x;
            }
        }
        __syncthreads();
    }
    #pragma unroll
    for (int k = 0; k < 4; k++) {
        int y = ty + 8*k;
        if (y < PSFW) d_Ep[((vs*NE + zi)*PSFW + y)*32 + tx] = acc[k];
    }
}

// ---------------- stage B2: combine halves, intensity + per-z sum ----------------
__global__ void stageB2() {
    int zi = blockIdx.x;
    int tid = threadIdx.x;
    float local = 0.f;
    for (int l = tid; l < PSFW*PSFW; l += 256) {
        int y = l / PSFW, x = l % PSFW;
        float2 e0 = d_Ep[((0*NE + zi)*PSFW + y)*32 + x];
        float2 e1 = d_Ep[((1*NE + zi)*PSFW + y)*32 + x];
        float ex = e0.x + e1.x, ey = e0.y + e1.y;
        float inten = ex*ex + ey*ey;
        d_psf[zi*PSFW*PSFW + l] = inten;
        local += inten;
    }
    __shared__ float red[256];
    red[tid] = local;
    __syncthreads();
    for (int s = 128; s > 0; s >>= 1) {
        if (tid < s) red[tid] += red[tid + s];
        __syncthreads();
    }
    if (tid == 0) d_psfsum[zi] = red[0];
}

// ---------------- scatter: normalized psf onto canvas ----------------
__global__ void scatter_k(const int* __restrict__ xyz) {
    int e = blockIdx.x & 63;
    int b = blockIdx.x >> 6;
    float scale = 1000000.0f / (d_psfsum[e] + 1e-12f);
    int r0 = xyz[(b*NE + e)*2 + 0];
    int c0 = xyz[(b*NE + e)*2 + 1];
    for (int p = threadIdx.x; p < PSFW*PSFW; p += 256) {
        int py = p / PSFW, px = p % PSFW;
        float val = d_psf[e*PSFW*PSFW + p] * scale;
        int row = r0 + py - R_;
        int col = c0 + px - R_;
        atomicAdd(&d_canvas[b*40000 + row*200 + col], val);
    }
}

// ---------------- blur (7x7, pad 2) + noise model ----------------
__global__ void blur_noise(const float* __restrict__ std_u,
                           const float* __restrict__ ed,
                           const float* __restrict__ ep,
                           const float* __restrict__ er,
                           float* __restrict__ out) {
    __shared__ float kern[49];
    if (threadIdx.x < 49) {
        float std = 0.8f + 0.4f * std_u[0];
        float s2 = std * std;
        int ky = threadIdx.x / 7 - 3, kx = threadIdx.x % 7 - 3;
        float g7 = expf(-(float)(kx*kx + ky*ky) * 0.5f);
        kern[threadIdx.x] = (1.0f / (2.0f * 3.14159265358979f * s2)) * powf(g7, 1.0f / s2);
    }
    __syncthreads();

    int idx = blockIdx.x * blockDim.x + threadIdx.x;
    if (idx >= TOT_OUT) return;
    int b = idx / (OUTW*OUTW);
    int rem = idx % (OUTW*OUTW);
    int y = rem / OUTW, x = rem % OUTW;

    float acc = 0.f;
    #pragma unroll
    for (int ky = 0; ky < 7; ky++) {
        int iy = y + ky - 2;
        if (iy < 0 || iy >= 200) continue;
        #pragma unroll
        for (int kx = 0; kx < 7; kx++) {
            int ix = x + kx - 2;
            if (ix < 0 || ix >= 200) continue;
            acc += kern[ky*7 + kx] * d_canvas[b*40000 + iy*200 + ix];
        }
    }

    float sig   = acc * 0.9f;
    float dark  = 0.005f + ed[idx] * 0.07071067811865475f;   // sqrt(0.005)
    float total = fmaxf(sig + dark, 0.f);
    float noisy = total + ep[idx] * sqrtf(fmaxf(total, 1e-12f));
    float elec  = noisy + er[idx] * 1.6f;
    float adu   = fminf(fmaxf(elec * 2.0f, 0.f), 65535.0f);
    float o     = (adu <= 10.0f) ? 1.0f : fminf(adu, 4.0e9f);
    out[idx] = o / 4.0e9f;
}

// ---------------- launch ----------------
extern "C" void kernel_launch(void* const* d_in, const int* in_sizes, int n_in,
                              void* d_out, int out_size) {
    const float* phase_mask = (const float*)d_in[0];
    const float* zs         = (const float*)d_in[1];
    const int*   xyz        = (const int*)  d_in[2];
    const float* std_u      = (const float*)d_in[3];
    const float* eps_dark   = (const float*)d_in[4];
    const float* eps_photon = (const float*)d_in[5];
    const float* eps_read   = (const float*)d_in[6];
    float* out = (float*)d_out;

    prep0<<<2, 256>>>();
    prep1<<<dim3(2, NN), 256>>>(phase_mask);
    prep2<<<(BB*200*200 + 255)/256, 256>>>();

    // radix-4 forward transforms: 4 x (500x125x125) per stage, split-K x2 + combine
    gemmS1<<<dim3(2, 8, 8), 256>>>();                      // slices [p*2+ks]
    combine1<<<(NN*NN + 255)/256, 256>>>();                // -> d_tq (row-parity split)
    gemmS2<<<dim3(8, 2, 8), 256>>>();
    combine2<<<(NN*NN + 255)/256, 256>>>();                // -> d_Ef

    stageA<<<dim3((NN + VT2 - 1)/VT2, NE), 256>>>(zs);
    stageB1<<<dim3(2, NE), dim3(32, 8)>>>();
    stageB2<<<NE, 256>>>();
    scatter_k<<<BB*NE, 256>>>(xyz);
    blur_noise<<<(TOT_OUT + 255)/256, 256>>>(std_u, eps_dark, eps_photon, eps_read, out);
}

// round 17
// speedup vs baseline: 1.5823x; 1.5823x over previous
#include <cuda_runtime.h>
#include <math.h>

// ---------------- constants ----------------
#define NN 500
#define NQ 125               // NN/4
#define PXd 1e-6
#define WLd 5.32e-7
#define FLd 0.1
#define FWHCd 1.5e-4
#define TWO_PI 6.283185307179586476925286766559
#define R_ 15
#define PSFW 31              // 2R+1
#define BB 8
#define NE 64
#define OUTW 198
#define TOT_OUT (BB*OUTW*OUTW)

// ---------------- device scratch (no runtime allocation allowed) ----------------
__device__ float2 d_fq[4*NN*NQ];     // field split by col parity mod 4 [p][500x125]
__device__ float2 d_F125[NQ*NQ];     // 125-pt DFT matrix (symmetric)
__device__ float  d_q[NN*NN];        // gamma/WL
__device__ float2 d_tq[4*NQ*NN];     // tmp split by row parity mod 4 [p][125x500]
__device__ float2 d_Ef[NN*NN];
__device__ float2 d_part[16*NN*NQ];  // split partials: 16 slices of 62500 (8 MB)
__device__ float2 d_W1[PSFW*NN];     // (1/N) e^{+2pi i u*(235+y)/N}
__device__ float2 d_T[NE*PSFW*NN];   // stage-A output
__device__ float2 d_Ep[2*NE*PSFW*32];// stage-B v-split partials
__device__ float  d_psf[NE*PSFW*PSFW];
__device__ float  d_psfsum[NE];
__device__ float  d_canvas[BB*200*200];
__device__ float2 d_tw[NN];          // e^{-2pi i m / 500}
__device__ double d_w2d[NN];         // (WL * fftfreq)^2, double

__device__ __forceinline__ void cmac(float2& a, float2 x, float2 y) {
    a.x += x.x*y.x - x.y*y.y;
    a.y += x.x*y.y + x.y*y.x;
}
__device__ __forceinline__ float2 cmul(float2 x, float2 y) {
    return make_float2(x.x*y.x - x.y*y.y, x.x*y.y + x.y*y.x);
}

// ---------------- prep 0: twiddle table + freq^2 table (500 DP ops total) ----------------
__global__ void prep0() {
    int m = blockIdx.x * blockDim.x + threadIdx.x;
    if (m >= NN) return;
    double ang = -TWO_PI * (double)m / (double)NN;
    double s, c;
    sincos(ang, &s, &c);
    d_tw[m] = make_float2((float)c, (float)s);
    double f = (double)((m < NN/2) ? m : m - NN) / ((double)NN * PXd);
    double w = WLd * f;
    d_w2d[m] = w * w;
}

// ---------------- prep 1: field (split cols mod 4) + q (table-driven, no DP divs) ----------------
__global__ void prep1(const float* __restrict__ phase_mask) {
    int j = blockIdx.x * blockDim.x + threadIdx.x;
    int i = blockIdx.y;
    if (j >= NN) return;
    int idx = i*NN + j;

    float xi = (float)((i - NN/2) * PXd);
    float xj = (float)((j - NN/2) * PXd);
    float r2 = xi*xi + xj*xj;
    float inc = expf(-r2 * (float)(1.0/(2.0*FWHCd*FWHCd)));
    float c1 = (float)(3.141592653589793/(WLd*FLd)) * r2;   // small arg, no fmod
    float b1s, b1c;
    __sincosf(c1, &b1s, &b1c);
    b1s = -b1s;                                // exp(-i c1)

    float p = phase_mask[idx];
    float ps, pc;
    __sincosf(p, &ps, &pc);
    float2 f;
    f.x = inc * (pc*b1c - ps*b1s);
    f.y = inc * (pc*b1s + ps*b1c);
    d_fq[(j & 3)*(NN*NQ) + i*NQ + (j >> 2)] = f;

    // gamma arg: 2 cheap DP adds from table, then f32 sqrt
    float arg = (float)(1.0 - d_w2d[i] - d_w2d[j]);
    float gf = (arg > 0.f) ? sqrtf(arg) : 0.f;
    d_q[idx] = gf * (float)(1.0/WLd);
}

// ---------------- prep 2: W1, F125, zero canvas ----------------
__global__ void prep2() {
    int tid = blockIdx.x * blockDim.x + threadIdx.x;
    if (tid < PSFW*NN) {
        int y = tid / NN, u = tid % NN;
        int m = (u * (235 + y)) % NN;
        float2 t = d_tw[m];
        d_W1[tid] = make_float2(t.x * (1.0f/NN), -t.y * (1.0f/NN));
    }
    if (tid < NQ*NQ) {
        int a = tid / NQ, b = tid % NQ;
        d_F125[tid] = d_tw[(4*a*b) % NN];    // e^{-2pi i a b / 125}
    }
    if (tid < BB*200*200) d_canvas[tid] = 0.0f;
}

// ---------------- generic complex GEMM body, 64x64 tile, 4x4/thread ----------------
#define KT 16
__device__ __forceinline__ void cgemm_body(const float2* __restrict__ A, int lda,
                                           const float2* __restrict__ B, int ldb,
                                           float2* __restrict__ P,
                                           int M, int N, int kbeg, int kend) {
    __shared__ float2 As[2][KT][66];
    __shared__ float2 Bs[2][KT][66];
    int tid = threadIdx.x;
    int tx = tid & 15, ty = tid >> 4;
    int i0 = blockIdx.y * 64, j0 = blockIdx.x * 64;
    const float2 zero = make_float2(0.f, 0.f);
    float2 acc[4][4] = {};

    auto load_tile = [&](int k0, int b) {
        #pragma unroll
        for (int l = tid; l < 64*KT; l += 256) {       // A: coalesced over k
            int kk = l & 15, ii = l >> 4;
            int i = i0 + ii, k = k0 + kk;
            As[b][kk][ii] = (i < M && k < kend) ? A[i*lda + k] : zero;
        }
        #pragma unroll
        for (int l = tid; l < 64*KT; l += 256) {       // B: coalesced over j
            int jj = l & 63, kk = l >> 6;
            int j = j0 + jj, k = k0 + kk;
            Bs[b][kk][jj] = (j < N && k < kend) ? B[k*ldb + j] : zero;
        }
    };

    int nkt = (kend - kbeg + KT - 1) / KT;
    load_tile(kbeg, 0);
    __syncthreads();

    for (int t = 0; t < nkt; t++) {
        int cb = t & 1;
        if (t + 1 < nkt) load_tile(kbeg + (t + 1)*KT, cb ^ 1);
        #pragma unroll
        for (int kk = 0; kk < KT; kk++) {
            float4 a01 = *(const float4*)&As[cb][kk][4*ty];
            float4 a23 = *(const float4*)&As[cb][kk][4*ty + 2];
            float4 b01 = *(const float4*)&Bs[cb][kk][4*tx];
            float4 b23 = *(const float4*)&Bs[cb][kk][4*tx + 2];
            float2 a[4] = {{a01.x,a01.y},{a01.z,a01.w},{a23.x,a23.y},{a23.z,a23.w}};
            float2 b[4] = {{b01.x,b01.y},{b01.z,b01.w},{b23.x,b23.y},{b23.z,b23.w}};
            #pragma unroll
            for (int r = 0; r < 4; r++)
                #pragma unroll
                for (int c = 0; c < 4; c++)
                    cmac(acc[r][c], a[r], b[c]);
        }
        __syncthreads();
    }

    #pragma unroll
    for (int r = 0; r < 4; r++) {
        int i = i0 + 4*ty + r;
        if (i >= M) continue;
        #pragma unroll
        for (int c = 0; c < 4; c++) {
            int j = j0 + 4*tx + c;
            if (j < N) P[i*N + j] = acc[r][c];
        }
    }
}

// stage 1 gemms: S_p = field_p(500x125) @ F125(125x125), split-K x4 (chunks of 32)
__global__ void __launch_bounds__(256, 2) gemmS1() {
    int p = blockIdx.z >> 2, ks = blockIdx.z & 3;
    int kbeg = ks * 32, kend = min(kbeg + 32, NQ);
    cgemm_body(d_fq + p*(NN*NQ), NQ, d_F125, NQ,
               d_part + blockIdx.z * (NN*NQ), NN, NQ, kbeg, kend);
}

// combine 1: tmp[i,k] = sum_p tw[(k*p)%500] * S_p[i, k%125]; write split by i mod 4
__global__ void combine1() {
    int idx = blockIdx.x * blockDim.x + threadIdx.x;
    if (idx >= NN*NN) return;
    int i = idx / NN, k = idx % NN;
    int a = k % NQ;
    int base = i*NQ + a;
    float2 S[4];
    #pragma unroll
    for (int p = 0; p < 4; p++) {
        float2 s0 = d_part[(p*4+0)*(NN*NQ) + base];
        float2 s1 = d_part[(p*4+1)*(NN*NQ) + base];
        float2 s2 = d_part[(p*4+2)*(NN*NQ) + base];
        float2 s3 = d_part[(p*4+3)*(NN*NQ) + base];
        S[p] = make_float2(s0.x+s1.x+s2.x+s3.x, s0.y+s1.y+s2.y+s3.y);
    }
    float2 acc = S[0];
    float2 c1 = cmul(d_tw[k % NN], S[1]);
    float2 c2 = cmul(d_tw[(2*k) % NN], S[2]);
    float2 c3 = cmul(d_tw[(3*k) % NN], S[3]);
    acc.x += c1.x + c2.x + c3.x;
    acc.y += c1.y + c2.y + c3.y;
    d_tq[(i & 3)*(NQ*NN) + (i >> 2)*NN + k] = acc;
}

// stage 2 gemms: U_p = F125(125x125) @ tmp_p(125x500), split-K x4
__global__ void __launch_bounds__(256, 2) gemmS2() {
    int p = blockIdx.z >> 2, ks = blockIdx.z & 3;
    int kbeg = ks * 32, kend = min(kbeg + 32, NQ);
    cgemm_body(d_F125, NQ, d_tq + p*(NQ*NN), NN,
               d_part + blockIdx.z * (NQ*NN), NQ, NN, kbeg, kend);
}

// combine 2: Ef[a,b] = sum_p tw[(a*p)%500] * U_p[a%125, b]
__global__ void combine2() {
    int idx = blockIdx.x * blockDim.x + threadIdx.x;
    if (idx >= NN*NN) return;
    int a = idx / NN, b = idx % NN;
    int base = (a % NQ)*NN + b;
    float2 U[4];
    #pragma unroll
    for (int p = 0; p < 4; p++) {
        float2 s0 = d_part[(p*4+0)*(NQ*NN) + base];
        float2 s1 = d_part[(p*4+1)*(NQ*NN) + base];
        float2 s2 = d_part[(p*4+2)*(NQ*NN) + base];
        float2 s3 = d_part[(p*4+3)*(NQ*NN) + base];
        U[p] = make_float2(s0.x+s1.x+s2.x+s3.x, s0.y+s1.y+s2.y+s3.y);
    }
    float2 acc = U[0];
    float2 c1 = cmul(d_tw[a % NN], U[1]);
    float2 c2 = cmul(d_tw[(2*a) % NN], U[2]);
    float2 c3 = cmul(d_tw[(3*a) % NN], U[3]);
    acc.x += c1.x + c2.x + c3.x;
    acc.y += c1.y + c2.y + c3.y;
    d_Ef[idx] = acc;
}

// ---------------- stage A (radix-4 pruned inverse DFT over u) ----------------
// T[z][y][v] = sum_{u<125} C_{c(y)}[u,v] * W1[y,u],  c(y) = (235+y) mod 4
#define UT2 12
#define VT2 64
#define CSZ (UT2*VT2)        // per-class chunk: 768 float2
#define WSZ (UT2*32)         // w pack: [du][ty][s], 384 float2
#define NCH ((NQ + UT2 - 1) / UT2)   // 11 chunks

__global__ void __launch_bounds__(256) stageA(const float* __restrict__ zs) {
    int zi = blockIdx.y;
    int v0 = blockIdx.x * VT2;
    int tid = threadIdx.x;
    int tx = tid & 31;                 // v pair -> v0+2tx, +1
    int ty = tid >> 5;                 // 0..7 ; ys = ty+8s, all same class
    float z = zs[zi];

    __shared__ float2 C_sh[4*CSZ];     // [4][UT2][VT2]
    __shared__ float2 w_sh[WSZ];       // [UT2][8][4]

    float2 acc[4][2] = {};             // [s][vp]
    int cls = (3 + ty) & 3;

    for (int t = 0; t < NCH; t++) {
        if (t) __syncthreads();
        int u0 = t * UT2;
        // ---- fill w pack ----
        for (int l = tid; l < WSZ; l += 256) {
            int du = l >> 5, r = l & 31;
            int tty = r >> 2, s = r & 3;
            int y = tty + 8*s;
            float2 w = make_float2(0.f, 0.f);
            if (y < PSFW && u0 + du < NQ) w = d_W1[y*NN + u0 + du];
            w_sh[l] = w;
        }
        // ---- fill C classes (modulate + 2-level butterfly) ----
        for (int l = tid; l < UT2*VT2; l += 256) {
            int du = l >> 6, lv = l & 63;
            int vv = v0 + lv;
            int ua = u0 + du;
            float2 g[4];
            if (vv < NN && ua < NQ) {
                #pragma unroll
                for (int k = 0; k < 4; k++) {
                    int idx = (ua + 125*k)*NN + vv;
                    float2 ef = d_Ef[idx];
                    float r = d_q[idx] * z;
                    r = r - rintf(r);
                    float s, c;
                    __sincosf(6.2831853071795864f * r, &s, &c);
                    g[k] = make_float2(ef.x*c - ef.y*s, ef.x*s + ef.y*c);
                }
            } else {
                g[0] = g[1] = g[2] = g[3] = make_float2(0.f, 0.f);
            }
            float2 A0 = make_float2(g[0].x + g[2].x, g[0].y + g[2].y);
            float2 A1 = make_float2(g[1].x + g[3].x, g[1].y + g[3].y);
            float2 B0 = make_float2(g[0].x - g[2].x, g[0].y - g[2].y);
            float2 B1 = make_float2(g[1].x - g[3].x, g[1].y - g[3].y);
            int off = du*VT2 + lv;
            C_sh[0*CSZ + off] = make_float2(A0.x + A1.x, A0.y + A1.y);
            C_sh[1*CSZ + off] = make_float2(B0.x - B1.y, B0.y + B1.x);  // B0 + i*B1
            C_sh[2*CSZ + off] = make_float2(A0.x - A1.x, A0.y - A1.y);
            C_sh[3*CSZ + off] = make_float2(B0.x + B1.y, B0.y - B1.x);  // B0 - i*B1
        }
        __syncthreads();
        // ---- accumulate ----
        const float2* Cc = C_sh + cls*CSZ;
        #pragma unroll
        for (int du = 0; du < UT2; du++) {
            float4 cv = *(const float4*)&Cc[du*VT2 + 2*tx];
            float2 c0 = make_float2(cv.x, cv.y), c1 = make_float2(cv.z, cv.w);
            const float2* wp = &w_sh[du*32 + ty*4];
            float4 wA = *(const float4*)(wp);
            float4 wB = *(const float4*)(wp + 2);
            float2 w0 = make_float2(wA.x, wA.y), w1 = make_float2(wA.z, wA.w);
            float2 w2 = make_float2(wB.x, wB.y), w3 = make_float2(wB.z, wB.w);
            cmac(acc[0][0], w0, c0); cmac(acc[0][1], w0, c1);
            cmac(acc[1][0], w1, c0); cmac(acc[1][1], w1, c1);
            cmac(acc[2][0], w2, c0); cmac(acc[2][1], w2, c1);
            cmac(acc[3][0], w3, c0); cmac(acc[3][1], w3, c1);
        }
    }
    #pragma unroll
    for (int s = 0; s < 4; s++) {
        int y = ty + 8*s;
        if (y >= PSFW) continue;
        #pragma unroll
        for (int vp = 0; vp < 2; vp++) {
            int v = v0 + 2*tx + vp;
            if (v < NN) d_T[(zi*PSFW + y)*NN + v] = acc[s][vp];
        }
    }
}

// ---------------- stage B1: E-partials over v halves (grid (2, NE)) ----------------
__global__ void stageB1() {
    int vs = blockIdx.x;                       // 0,1: v in [vs*250, vs*250+250)
    int zi = blockIdx.y;
    int tx = threadIdx.x;                      // 0..31 (x)
    int ty = threadIdx.y;                      // 0..7  (y stride 8)
    int tid = ty*32 + tx;
    int vbeg = vs * 250, vend = vbeg + 250;

    __shared__ float2 T_sh[PSFW*64];
    __shared__ float2 W_sh[64*32];             // [vl][x]
    float2 acc[4] = {};

    for (int v0 = vbeg; v0 < vend; v0 += 64) {
        for (int l = tid; l < PSFW*64; l += 256) {
            int y = l / 64, vl = l % 64;
            int v = v0 + vl;
            T_sh[l] = (v < vend) ? d_T[(zi*PSFW + y)*NN + v] : make_float2(0.f, 0.f);
        }
        for (int l = tid; l < 64*32; l += 256) {
            int vl = l / 32, x = l % 32;
            int v = v0 + vl;
            W_sh[l] = (v < vend && x < PSFW) ? d_W1[x*NN + v] : make_float2(0.f, 0.f);
        }
        __syncthreads();
        #pragma unroll 8
        for (int vl = 0; vl < 64; vl++) {
            float2 w = W_sh[vl*32 + tx];
            #pragma unroll
            for (int k = 0; k < 4; k++) {
                int y = ty + 8*k;
                float2 t = T_sh[(y < PSFW ? y : PSFW-1)*64 + vl];
                acc[k].x += t.x*w.x - t.y*w.y;
                acc[k].y += t.x*w.y + t.y*w.x;
            }
        }
        __syncthreads();
    }
    #pragma unroll
    for (int k = 0; k < 4; k++) {
        int y = ty + 8*k;
        if (y < PSFW) d_Ep[((vs*NE + zi)*PSFW + y)*32 + tx] = acc[k];
    }
}

// ---------------- stage B2: combine halves, intensity + per-z sum ----------------
__global__ void stageB2() {
    int zi = blockIdx.x;
    int tid = threadIdx.x;
    float local = 0.f;
    for (int l = tid; l < PSFW*PSFW; l += 256) {
        int y = l / PSFW, x = l % PSFW;
        float2 e0 = d_Ep[((0*NE + zi)*PSFW + y)*32 + x];
        float2 e1 = d_Ep[((1*NE + zi)*PSFW + y)*32 + x];
        float ex = e0.x + e1.x, ey = e0.y + e1.y;
        float inten = ex*ex + ey*ey;
        d_psf[zi*PSFW*PSFW + l] = inten;
        local += inten;
    }
    __shared__ float red[256];
    red[tid] = local;
    __syncthreads();
    for (int s = 128; s > 0; s >>= 1) {
        if (tid < s) red[tid] += red[tid + s];
        __syncthreads();
    }
    if (tid == 0) d_psfsum[zi] = red[0];
}

// ---------------- scatter: normalized psf onto canvas ----------------
__global__ void scatter_k(const int* __restrict__ xyz) {
    int e = blockIdx.x & 63;
    int b = blockIdx.x >> 6;
    float scale = 1000000.0f / (d_psfsum[e] + 1e-12f);
    int r0 = xyz[(b*NE + e)*2 + 0];
    int c0 = xyz[(b*NE + e)*2 + 1];
    for (int p = threadIdx.x; p < PSFW*PSFW; p += 256) {
        int py = p / PSFW, px = p % PSFW;
        float val = d_psf[e*PSFW*PSFW + p] * scale;
        int row = r0 + py - R_;
        int col = c0 + px - R_;
        atomicAdd(&d_canvas[b*40000 + row*200 + col], val);
    }
}

// ---------------- blur (7x7, pad 2) + noise model ----------------
__global__ void blur_noise(const float* __restrict__ std_u,
                           const float* __restrict__ ed,
                           const float* __restrict__ ep,
                           const float* __restrict__ er,
                           float* __restrict__ out) {
    __shared__ float kern[49];
    if (threadIdx.x < 49) {
        float std = 0.8f + 0.4f * std_u[0];
        float s2 = std * std;
        int ky = threadIdx.x / 7 - 3, kx = threadIdx.x % 7 - 3;
        float g7 = expf(-(float)(kx*kx + ky*ky) * 0.5f);
        kern[threadIdx.x] = (1.0f / (2.0f * 3.14159265358979f * s2)) * powf(g7, 1.0f / s2);
    }
    __syncthreads();

    int idx = blockIdx.x * blockDim.x + threadIdx.x;
    if (idx >= TOT_OUT) return;
    int b = idx / (OUTW*OUTW);
    int rem = idx % (OUTW*OUTW);
    int y = rem / OUTW, x = rem % OUTW;

    float acc = 0.f;
    #pragma unroll
    for (int ky = 0; ky < 7; ky++) {
        int iy = y + ky - 2;
        if (iy < 0 || iy >= 200) continue;
        #pragma unroll
        for (int kx = 0; kx < 7; kx++) {
            int ix = x + kx - 2;
            if (ix < 0 || ix >= 200) continue;
            acc += kern[ky*7 + kx] * d_canvas[b*40000 + iy*200 + ix];
        }
    }

    float sig   = acc * 0.9f;
    float dark  = 0.005f + ed[idx] * 0.07071067811865475f;   // sqrt(0.005)
    float total = fmaxf(sig + dark, 0.f);
    float noisy = total + ep[idx] * sqrtf(fmaxf(total, 1e-12f));
    float elec  = noisy + er[idx] * 1.6f;
    float adu   = fminf(fmaxf(elec * 2.0f, 0.f), 65535.0f);
    float o     = (adu <= 10.0f) ? 1.0f : fminf(adu, 4.0e9f);
    out[idx] = o / 4.0e9f;
}

// ---------------- launch ----------------
extern "C" void kernel_launch(void* const* d_in, const int* in_sizes, int n_in,
                              void* d_out, int out_size) {
    const float* phase_mask = (const float*)d_in[0];
    const float* zs         = (const float*)d_in[1];
    const int*   xyz        = (const int*)  d_in[2];
    const float* std_u      = (const float*)d_in[3];
    const float* eps_dark   = (const float*)d_in[4];
    const float* eps_photon = (const float*)d_in[5];
    const float* eps_read   = (const float*)d_in[6];
    float* out = (float*)d_out;

    prep0<<<2, 256>>>();
    prep1<<<dim3(2, NN), 256>>>(phase_mask);
    prep2<<<(BB*200*200 + 255)/256, 256>>>();

    // radix-4 forward transforms: 4 x (500x125x125) per stage, split-K x4 + combine
    gemmS1<<<dim3(2, 8, 16), 256>>>();                     // slices [p*4+ks]
    combine1<<<(NN*NN + 255)/256, 256>>>();                // -> d_tq (row-parity split)
    gemmS2<<<dim3(8, 2, 16), 256>>>();
    combine2<<<(NN*NN + 255)/256, 256>>>();                // -> d_Ef

    stageA<<<dim3((NN + VT2 - 1)/VT2, NE), 256>>>(zs);
    stageB1<<<dim3(2, NE), dim3(32, 8)>>>();
    stageB2<<<NE, 256>>>();
    scatter_k<<<BB*NE, 256>>>(xyz);
    blur_noise<<<(TOT_OUT + 255)/256, 256>>>(std_u, eps_dark, eps_photon, eps_read, out);
}